// round 5
// baseline (speedup 1.0000x reference)
#include <cuda_runtime.h>
#include <cuda_bf16.h>
#include <cstdint>

#define Bn 64
#define Qn 2048
#define Kn 2048
#define Dn 128

// ---------------- scratch (device globals; no allocation) ----------------
__device__ __align__(256) __nv_bfloat16 g_qh[(size_t)Bn * Qn * Dn];
__device__ __align__(256) __nv_bfloat16 g_ql[(size_t)Bn * Qn * Dn];
__device__ __align__(256) __nv_bfloat16 g_kh[(size_t)Bn * Kn * Dn];
__device__ __align__(256) __nv_bfloat16 g_kl[(size_t)Bn * Kn * Dn];
__device__ __align__(256) __nv_bfloat16 g_vth[(size_t)Bn * Dn * Kn];  // [b][d][k]
__device__ __align__(256) __nv_bfloat16 g_vtl[(size_t)Bn * Dn * Kn];
__device__ __align__(256) float g_pm[(size_t)Bn * Qn * 32];   // partial max per 64-col block
__device__ __align__(256) float g_ps[(size_t)Bn * Qn * 32];   // partial sumexp
__device__ __align__(256) float g_m [(size_t)Bn * Qn];        // row max
__device__ __align__(256) float g_is[(size_t)Bn * Qn];        // 1/row sum

// ---------------- helpers ----------------
#define MMA_BF16(C, a0, a1, a2, a3, b0, b1)                                   \
  asm volatile(                                                               \
      "mma.sync.aligned.m16n8k16.row.col.f32.bf16.bf16.f32 "                  \
      "{%0,%1,%2,%3}, {%4,%5,%6,%7}, {%8,%9}, {%0,%1,%2,%3};\n"               \
      : "+f"(C[0]), "+f"(C[1]), "+f"(C[2]), "+f"(C[3])                        \
      : "r"(a0), "r"(a1), "r"(a2), "r"(a3), "r"(b0), "r"(b1))

__device__ __forceinline__ void splitpack(float x, float y, uint32_t& h, uint32_t& l) {
    __nv_bfloat162 hh = __floats2bfloat162_rn(x, y);
    float hx = __low2float(hh);
    float hy = __high2float(hh);
    __nv_bfloat162 ll = __floats2bfloat162_rn(x - hx, y - hy);
    h = *reinterpret_cast<uint32_t*>(&hh);
    l = *reinterpret_cast<uint32_t*>(&ll);
}
__device__ __forceinline__ uint32_t smem_u32(const void* p) {
    return (uint32_t)__cvta_generic_to_shared(p);
}
__device__ __forceinline__ void cpasync16(uint32_t dst, const void* src) {
    asm volatile("cp.async.cg.shared.global [%0], [%1], 16;\n" :: "r"(dst), "l"(src));
}
#define CP_COMMIT asm volatile("cp.async.commit_group;\n" ::: "memory")
#define CP_WAIT0  asm volatile("cp.async.wait_group 0;\n" ::: "memory")

// ================= K0a: fp32 -> (hi, lo) bf16 =================
__global__ void __launch_bounds__(256)
convert_kernel(const float* __restrict__ x, __nv_bfloat16* __restrict__ h,
               __nv_bfloat16* __restrict__ l)
{
    int i = blockIdx.x * 256 + threadIdx.x;   // float4 index; grid covers exactly
    float4 v = ((const float4*)x)[i];
    uint32_t h0, l0, h1, l1;
    splitpack(v.x, v.y, h0, l0);
    splitpack(v.z, v.w, h1, l1);
    ((uint2*)h)[i] = make_uint2(h0, h1);
    ((uint2*)l)[i] = make_uint2(l0, l1);
}

// ================= K0b: V fp32 [b][k][d] -> bf16 hi/lo [b][d][k] =================
__global__ void __launch_bounds__(256)
transpose_conv_kernel(const float* __restrict__ v,
                      __nv_bfloat16* __restrict__ th, __nv_bfloat16* __restrict__ tl)
{
    __shared__ float t[32][33];
    const int b  = blockIdx.z;
    const int k0 = blockIdx.x * 32;
    const int d0 = blockIdx.y * 32;
    const int tx = threadIdx.x & 31;
    const int ty = threadIdx.x >> 5;
#pragma unroll
    for (int i = 0; i < 4; i++) {
        int k = ty + i * 8;
        t[k][tx] = v[((size_t)b * Kn + k0 + k) * Dn + d0 + tx];
    }
    __syncthreads();
#pragma unroll
    for (int i = 0; i < 4; i++) {
        int d = ty + i * 8;
        float x = t[tx][d];
        __nv_bfloat16 hb = __float2bfloat16_rn(x);
        __nv_bfloat16 lb = __float2bfloat16_rn(x - __bfloat162float(hb));
        size_t o = ((size_t)b * Dn + d0 + d) * Kn + k0 + tx;
        th[o] = hb;
        tl[o] = lb;
    }
}

// ================= K1: scores GEMM (pure bf16) + masked partial stats =================
// Writes MASKED scaled scores (masked -> -1e9) into attn region, plus per-row
// per-64-col-block (max, sumexp) partials.
#define K1S 136                  /* bf16 row stride */
#define K1_ARR (128 * K1S * 2)   /* 34816 bytes per array */
#define K1_SMEM (4 * K1_ARR)     /* 139264 */

__global__ void __launch_bounds__(256, 1)
scores_kernel(const __nv_bfloat16* __restrict__ qh, const __nv_bfloat16* __restrict__ ql,
              const __nv_bfloat16* __restrict__ kh, const __nv_bfloat16* __restrict__ kl,
              const int* __restrict__ vlg,
              float* __restrict__ sg, float* __restrict__ pm, float* __restrict__ ps)
{
    extern __shared__ unsigned char sm[];
    __nv_bfloat16* sQh = (__nv_bfloat16*)(sm);
    __nv_bfloat16* sQl = (__nv_bfloat16*)(sm + K1_ARR);
    __nv_bfloat16* sKh = (__nv_bfloat16*)(sm + 2 * K1_ARR);
    __nv_bfloat16* sKl = (__nv_bfloat16*)(sm + 3 * K1_ARR);

    const int b  = blockIdx.z;
    const int i0 = blockIdx.y * 128;
    const int j0 = blockIdx.x * 128;
    const int tid = threadIdx.x;
    const int w = tid >> 5, lane = tid & 31;
    const int g = lane >> 2, ct = lane & 3;
    const int wm = w >> 1, wn = w & 1;
    const int VL = vlg[b];

    const __nv_bfloat16* gq[2] = { qh + ((size_t)b * Qn + i0) * Dn,
                                   ql + ((size_t)b * Qn + i0) * Dn };
    const __nv_bfloat16* gk[2] = { kh + ((size_t)b * Kn + j0) * Dn,
                                   kl + ((size_t)b * Kn + j0) * Dn };
    uint32_t dq[2] = { smem_u32(sQh), smem_u32(sQl) };
    uint32_t dk[2] = { smem_u32(sKh), smem_u32(sKl) };

    // 4 commit groups, one per D-quarter (cols q*32 .. q*32+31)
#pragma unroll
    for (int q = 0; q < 4; q++) {
#pragma unroll
        for (int rep = 0; rep < 8; rep++) {
            int arr = rep >> 1;                       // 0..3: Qh,Ql,Kh,Kl
            int rem = tid + (rep & 1) * 256;          // 0..511
            int r = rem >> 2;
            int c4 = q * 4 + (rem & 3);
            if (arr < 2)
                cpasync16(dq[arr] + r * (K1S * 2) + c4 * 16, gq[arr] + (size_t)r * Dn + c4 * 8);
            else
                cpasync16(dk[arr - 2] + r * (K1S * 2) + c4 * 16, gk[arr - 2] + (size_t)r * Dn + c4 * 8);
        }
        CP_COMMIT;
    }

    float acc[2][8][4] = {};
#pragma unroll
    for (int q = 0; q < 4; q++) {
        if (q == 0)      asm volatile("cp.async.wait_group 3;\n" ::: "memory");
        else if (q == 1) asm volatile("cp.async.wait_group 2;\n" ::: "memory");
        else if (q == 2) asm volatile("cp.async.wait_group 1;\n" ::: "memory");
        else             asm volatile("cp.async.wait_group 0;\n" ::: "memory");
        __syncthreads();
#pragma unroll
        for (int kt = 0; kt < 2; kt++) {
            const int kk = q * 2 + kt;
            uint32_t ah[2][4], al[2][4];
#pragma unroll
            for (int mf = 0; mf < 2; mf++) {
                const __nv_bfloat16* p0 = sQh + (wm * 32 + mf * 16 + g) * K1S + kk * 16 + 2 * ct;
                ah[mf][0] = *(const uint32_t*)p0;
                ah[mf][1] = *(const uint32_t*)(p0 + 8 * K1S);
                ah[mf][2] = *(const uint32_t*)(p0 + 8);
                ah[mf][3] = *(const uint32_t*)(p0 + 8 * K1S + 8);
                const __nv_bfloat16* p1 = sQl + (wm * 32 + mf * 16 + g) * K1S + kk * 16 + 2 * ct;
                al[mf][0] = *(const uint32_t*)p1;
                al[mf][1] = *(const uint32_t*)(p1 + 8 * K1S);
                al[mf][2] = *(const uint32_t*)(p1 + 8);
                al[mf][3] = *(const uint32_t*)(p1 + 8 * K1S + 8);
            }
#pragma unroll
            for (int nf = 0; nf < 8; nf++) {
                const __nv_bfloat16* kb = sKh + (wn * 64 + nf * 8 + g) * K1S + kk * 16 + 2 * ct;
                uint32_t bh0 = *(const uint32_t*)kb;
                uint32_t bh1 = *(const uint32_t*)(kb + 8);
                const __nv_bfloat16* kc = sKl + (wn * 64 + nf * 8 + g) * K1S + kk * 16 + 2 * ct;
                uint32_t bl0 = *(const uint32_t*)kc;
                uint32_t bl1 = *(const uint32_t*)(kc + 8);
#pragma unroll
                for (int mf = 0; mf < 2; mf++) {
                    MMA_BF16(acc[mf][nf], ah[mf][0], ah[mf][1], ah[mf][2], ah[mf][3], bh0, bh1);
                    MMA_BF16(acc[mf][nf], ah[mf][0], ah[mf][1], ah[mf][2], ah[mf][3], bl0, bl1);
                    MMA_BF16(acc[mf][nf], al[mf][0], al[mf][1], al[mf][2], al[mf][3], bh0, bh1);
                }
            }
        }
    }

    // ---- epilogue: scale, mask, store raw-masked scores, partial stats ----
    const float scale = 0.08838834764831845f;
    const int jt = blockIdx.x * 2 + wn;
#pragma unroll
    for (int mf = 0; mf < 2; mf++) {
#pragma unroll
        for (int h = 0; h < 2; h++) {
            const int r = wm * 32 + mf * 16 + h * 8 + g;
            float vals[16];
#pragma unroll
            for (int nf = 0; nf < 8; nf++) {
                int j = j0 + wn * 64 + nf * 8 + 2 * ct;
                float v0 = acc[mf][nf][2 * h]     * scale;
                float v1 = acc[mf][nf][2 * h + 1] * scale;
                vals[2 * nf]     = (j     < VL) ? v0 : -1e9f;
                vals[2 * nf + 1] = (j + 1 < VL) ? v1 : -1e9f;
            }
            float* srow = sg + ((size_t)b * Qn + i0 + r) * Kn + j0 + wn * 64;
#pragma unroll
            for (int nf = 0; nf < 8; nf++)
                *(float2*)(srow + nf * 8 + 2 * ct) = make_float2(vals[2 * nf], vals[2 * nf + 1]);

            float mx = vals[0];
#pragma unroll
            for (int t = 1; t < 16; t++) mx = fmaxf(mx, vals[t]);
            mx = fmaxf(mx, __shfl_xor_sync(0xffffffffu, mx, 1));
            mx = fmaxf(mx, __shfl_xor_sync(0xffffffffu, mx, 2));
            float se = 0.f;
#pragma unroll
            for (int t = 0; t < 16; t++) se += __expf(vals[t] - mx);
            se += __shfl_xor_sync(0xffffffffu, se, 1);
            se += __shfl_xor_sync(0xffffffffu, se, 2);
            if (ct == 0) {
                size_t o = ((size_t)b * Qn + i0 + r) * 32 + jt;
                pm[o] = mx;
                ps[o] = se;
            }
        }
    }
}

// ================= K1b: reduce partials -> row max + 1/sum =================
__global__ void __launch_bounds__(256)
reduce_kernel(const float* __restrict__ pm, const float* __restrict__ ps,
              float* __restrict__ mo, float* __restrict__ iso)
{
    int i = blockIdx.x * 256 + threadIdx.x;   // row id, grid covers Bn*Qn
    const float4* m4 = (const float4*)(pm + (size_t)i * 32);
    const float4* s4 = (const float4*)(ps + (size_t)i * 32);
    float4 mv[8];
    float m = -3.402823466e38f;
#pragma unroll
    for (int t = 0; t < 8; t++) {
        mv[t] = m4[t];
        m = fmaxf(m, fmaxf(fmaxf(mv[t].x, mv[t].y), fmaxf(mv[t].z, mv[t].w)));
    }
    float sum = 0.f;
#pragma unroll
    for (int t = 0; t < 8; t++) {
        float4 sv = s4[t];
        sum += sv.x * __expf(mv[t].x - m);
        sum += sv.y * __expf(mv[t].y - m);
        sum += sv.z * __expf(mv[t].z - m);
        sum += sv.w * __expf(mv[t].w - m);
    }
    mo[i]  = m;
    iso[i] = 1.0f / sum;
}

// ================= K2b: normalize + attn writeback + PV GEMM =================
#define PS 68     /* float stride, S tile (k-contiguous) */
#define VS 72     /* bf16 stride, Vt tile rows d, cols k  */
#define K2_OFF_S  0
#define K2_SZ_S   (128 * PS * 4)          /* 34816 */
#define K2_OFF_VH (K2_SZ_S)
#define K2_SZ_V   (128 * VS * 2)          /* 18432 */
#define K2_OFF_VL (K2_OFF_VH + K2_SZ_V)
#define K2_SMEM   (K2_OFF_VL + K2_SZ_V)   /* 71680 */

__global__ void __launch_bounds__(256, 2)
pv_kernel(float* __restrict__ att,                     // in: masked scores, out: attn
          const __nv_bfloat16* __restrict__ vth, const __nv_bfloat16* __restrict__ vtl,
          const float* __restrict__ mg, const float* __restrict__ isg,
          float* __restrict__ outg)
{
    extern __shared__ unsigned char sm[];
    float*         sS  = (float*)(sm + K2_OFF_S);
    __nv_bfloat16* sVh = (__nv_bfloat16*)(sm + K2_OFF_VH);
    __nv_bfloat16* sVl = (__nv_bfloat16*)(sm + K2_OFF_VL);

    const int b  = blockIdx.y;
    const int i0 = blockIdx.x * 128;
    const int tid = threadIdx.x;
    const int w = tid >> 5, lane = tid & 31;
    const int g = lane >> 2, ct = lane & 3;
    const int wm = w >> 1, wn = w & 1;

    float* Sg = att + ((size_t)b * Qn + i0) * Kn;
    const __nv_bfloat16* vh_g = vth + (size_t)b * Dn * Kn;
    const __nv_bfloat16* vl_g = vtl + (size_t)b * Dn * Kn;
    uint32_t sS_u  = smem_u32(sS);
    uint32_t sVh_u = smem_u32(sVh);
    uint32_t sVl_u = smem_u32(sVl);

    // per-thread row stats (rows wm*32 + mf*16 + h*8 + g)
    float rm[2][2], ris[2][2];
#pragma unroll
    for (int mf = 0; mf < 2; mf++)
#pragma unroll
        for (int h = 0; h < 2; h++) {
            size_t idx = (size_t)b * Qn + i0 + wm * 32 + mf * 16 + h * 8 + g;
            rm[mf][h]  = mg[idx];
            ris[mf][h] = isg[idx];
        }

    float acc[2][8][4] = {};

    for (int c0 = 0; c0 < Kn; c0 += 64) {
        __syncthreads();
        // S chunk: 128 rows x 64 floats
#pragma unroll
        for (int rep = 0; rep < 8; rep++) {
            int idx = tid + rep * 256;          // 0..2047
            int r = idx >> 4, c4 = idx & 15;
            cpasync16(sS_u + r * (PS * 4) + c4 * 16, Sg + (size_t)r * Kn + c0 + c4 * 4);
        }
        // Vt chunks: hi/lo, 128 d-rows x 64 bf16
#pragma unroll
        for (int rep = 0; rep < 8; rep++) {
            int arr = rep >> 2;                 // 0: hi, 1: lo
            int rem = tid + (rep & 3) * 256;    // 0..1023
            int d = rem >> 3, c4 = rem & 7;
            if (arr == 0)
                cpasync16(sVh_u + d * (VS * 2) + c4 * 16, vh_g + (size_t)d * Kn + c0 + c4 * 8);
            else
                cpasync16(sVl_u + d * (VS * 2) + c4 * 16, vl_g + (size_t)d * Kn + c0 + c4 * 8);
        }
        CP_COMMIT; CP_WAIT0;
        __syncthreads();

#pragma unroll
        for (int kk = 0; kk < 4; kk++) {
            uint32_t ah[2][4], al[2][4];
#pragma unroll
            for (int mf = 0; mf < 2; mf++) {
                const float* sp = sS + (wm * 32 + mf * 16 + g) * PS + kk * 16 + 2 * ct;
                float2 s0 = *(const float2*)sp;
                float2 s1 = *(const float2*)(sp + 8 * PS);
                float2 s2 = *(const float2*)(sp + 8);
                float2 s3 = *(const float2*)(sp + 8 * PS + 8);
                float m0 = rm[mf][0], i0v = ris[mf][0];
                float m1 = rm[mf][1], i1v = ris[mf][1];
                float2 p0 = { __expf(s0.x - m0) * i0v, __expf(s0.y - m0) * i0v };
                float2 p1 = { __expf(s1.x - m1) * i1v, __expf(s1.y - m1) * i1v };
                float2 p2 = { __expf(s2.x - m0) * i0v, __expf(s2.y - m0) * i0v };
                float2 p3 = { __expf(s3.x - m1) * i1v, __expf(s3.y - m1) * i1v };
                if (wn == 0) {
                    float* arow = Sg + (size_t)(wm * 32 + mf * 16 + g) * Kn + c0 + kk * 16 + 2 * ct;
                    *(float2*)(arow)              = p0;
                    *(float2*)(arow + 8 * Kn)     = p1;
                    *(float2*)(arow + 8)          = p2;
                    *(float2*)(arow + 8 * Kn + 8) = p3;
                }
                splitpack(p0.x, p0.y, ah[mf][0], al[mf][0]);
                splitpack(p1.x, p1.y, ah[mf][1], al[mf][1]);
                splitpack(p2.x, p2.y, ah[mf][2], al[mf][2]);
                splitpack(p3.x, p3.y, ah[mf][3], al[mf][3]);
            }
#pragma unroll
            for (int nf = 0; nf < 8; nf++) {
                const __nv_bfloat16* vb = sVh + (wn * 64 + nf * 8 + g) * VS + kk * 16 + 2 * ct;
                uint32_t bh0 = *(const uint32_t*)vb;
                uint32_t bh1 = *(const uint32_t*)(vb + 8);
                const __nv_bfloat16* vc = sVl + (wn * 64 + nf * 8 + g) * VS + kk * 16 + 2 * ct;
                uint32_t bl0 = *(const uint32_t*)vc;
                uint32_t bl1 = *(const uint32_t*)(vc + 8);
#pragma unroll
                for (int mf = 0; mf < 2; mf++) {
                    MMA_BF16(acc[mf][nf], ah[mf][0], ah[mf][1], ah[mf][2], ah[mf][3], bh0, bh1);
                    MMA_BF16(acc[mf][nf], ah[mf][0], ah[mf][1], ah[mf][2], ah[mf][3], bl0, bl1);
                    MMA_BF16(acc[mf][nf], al[mf][0], al[mf][1], al[mf][2], al[mf][3], bh0, bh1);
                }
            }
        }
    }

    float* op = outg + ((size_t)b * Qn + i0) * Dn;
#pragma unroll
    for (int mf = 0; mf < 2; mf++)
#pragma unroll
        for (int nf = 0; nf < 8; nf++) {
            int row = wm * 32 + mf * 16 + g;
            int col = wn * 64 + nf * 8 + 2 * ct;
            *(float2*)(op + (size_t)row * Dn + col)       = make_float2(acc[mf][nf][0], acc[mf][nf][1]);
            *(float2*)(op + (size_t)(row + 8) * Dn + col) = make_float2(acc[mf][nf][2], acc[mf][nf][3]);
        }
}

// ================= launch =================
extern "C" void kernel_launch(void* const* d_in, const int* in_sizes, int n_in,
                              void* d_out, int out_size) {
    const float* q  = (const float*)d_in[0];
    const float* k  = (const float*)d_in[1];
    const float* v  = (const float*)d_in[2];
    const int*   vl = (const int*)d_in[3];
    float* out  = (float*)d_out;
    float* attn = out + (size_t)Bn * Qn * Dn;   // output tuple: (out, attn)

    void *p_qh, *p_ql, *p_kh, *p_kl, *p_vth, *p_vtl, *p_pm, *p_ps, *p_m, *p_is;
    cudaGetSymbolAddress(&p_qh, g_qh);
    cudaGetSymbolAddress(&p_ql, g_ql);
    cudaGetSymbolAddress(&p_kh, g_kh);
    cudaGetSymbolAddress(&p_kl, g_kl);
    cudaGetSymbolAddress(&p_vth, g_vth);
    cudaGetSymbolAddress(&p_vtl, g_vtl);
    cudaGetSymbolAddress(&p_pm, g_pm);
    cudaGetSymbolAddress(&p_ps, g_ps);
    cudaGetSymbolAddress(&p_m,  g_m);
    cudaGetSymbolAddress(&p_is, g_is);

    cudaFuncSetAttribute(scores_kernel, cudaFuncAttributeMaxDynamicSharedMemorySize, K1_SMEM);
    cudaFuncSetAttribute(pv_kernel,     cudaFuncAttributeMaxDynamicSharedMemorySize, K2_SMEM);

    const int n4 = Bn * Qn * Dn / 4;   // 4194304
    convert_kernel<<<n4 / 256, 256>>>(q, (__nv_bfloat16*)p_qh, (__nv_bfloat16*)p_ql);
    convert_kernel<<<n4 / 256, 256>>>(k, (__nv_bfloat16*)p_kh, (__nv_bfloat16*)p_kl);
    transpose_conv_kernel<<<dim3(Kn / 32, Dn / 32, Bn), 256>>>(v, (__nv_bfloat16*)p_vth,
                                                               (__nv_bfloat16*)p_vtl);

    scores_kernel<<<dim3(Kn / 128, Qn / 128, Bn), 256, K1_SMEM>>>(
        (const __nv_bfloat16*)p_qh, (const __nv_bfloat16*)p_ql,
        (const __nv_bfloat16*)p_kh, (const __nv_bfloat16*)p_kl,
        vl, attn, (float*)p_pm, (float*)p_ps);

    reduce_kernel<<<Bn * Qn / 256, 256>>>((const float*)p_pm, (const float*)p_ps,
                                          (float*)p_m, (float*)p_is);

    pv_kernel<<<dim3(Qn / 128, Bn), 256, K2_SMEM>>>(
        attn, (const __nv_bfloat16*)p_vth, (const __nv_bfloat16*)p_vtl,
        (const float*)p_m, (const float*)p_is, out);
}

// round 7
// speedup vs baseline: 1.6601x; 1.6601x over previous
#include <cuda_runtime.h>
#include <cuda_bf16.h>
#include <cstdint>

#define Bn 64
#define Qn 2048
#define Kn 2048
#define Dn 128

// ---------------- scratch (device globals; no allocation) ----------------
__device__ __align__(256) __nv_bfloat16 g_qh[(size_t)Bn * Qn * Dn];
__device__ __align__(256) __nv_bfloat16 g_ql[(size_t)Bn * Qn * Dn];
__device__ __align__(256) __nv_bfloat16 g_kh[(size_t)Bn * Kn * Dn];
__device__ __align__(256) __nv_bfloat16 g_kl[(size_t)Bn * Kn * Dn];
__device__ __align__(256) __nv_bfloat16 g_vth[(size_t)Bn * Dn * Kn];  // [b][d][k]
__device__ __align__(256) __nv_bfloat16 g_vtl[(size_t)Bn * Dn * Kn];
__device__ __align__(256) float g_ps[(size_t)Bn * Qn * 32];   // partial sumexp per 64-col block
__device__ __align__(256) float g_is[(size_t)Bn * Qn];        // 1/row sum

// ---------------- helpers ----------------
#define MMA_BF16(C, a0, a1, a2, a3, b0, b1)                                   \
  asm volatile(                                                               \
      "mma.sync.aligned.m16n8k16.row.col.f32.bf16.bf16.f32 "                  \
      "{%0,%1,%2,%3}, {%4,%5,%6,%7}, {%8,%9}, {%0,%1,%2,%3};\n"               \
      : "+f"(C[0]), "+f"(C[1]), "+f"(C[2]), "+f"(C[3])                        \
      : "r"(a0), "r"(a1), "r"(a2), "r"(a3), "r"(b0), "r"(b1))

__device__ __forceinline__ void splitpack(float x, float y, uint32_t& h, uint32_t& l) {
    __nv_bfloat162 hh = __floats2bfloat162_rn(x, y);
    float hx = __low2float(hh);
    float hy = __high2float(hh);
    __nv_bfloat162 ll = __floats2bfloat162_rn(x - hx, y - hy);
    h = *reinterpret_cast<uint32_t*>(&hh);
    l = *reinterpret_cast<uint32_t*>(&ll);
}
__device__ __forceinline__ uint32_t smem_u32(const void* p) {
    return (uint32_t)__cvta_generic_to_shared(p);
}
__device__ __forceinline__ void cpasync16(uint32_t dst, const void* src) {
    asm volatile("cp.async.cg.shared.global [%0], [%1], 16;\n" :: "r"(dst), "l"(src));
}
#define CP_COMMIT asm volatile("cp.async.commit_group;\n" ::: "memory")
#define CP_WAIT0  asm volatile("cp.async.wait_group 0;\n" ::: "memory")

// ================= K0a: fp32 -> (hi, lo) bf16 =================
__global__ void __launch_bounds__(256)
convert_kernel(const float* __restrict__ x, __nv_bfloat16* __restrict__ h,
               __nv_bfloat16* __restrict__ l)
{
    int i = blockIdx.x * 256 + threadIdx.x;
    float4 v = ((const float4*)x)[i];
    uint32_t h0, l0, h1, l1;
    splitpack(v.x, v.y, h0, l0);
    splitpack(v.z, v.w, h1, l1);
    ((uint2*)h)[i] = make_uint2(h0, h1);
    ((uint2*)l)[i] = make_uint2(l0, l1);
}

// ================= K0b: V fp32 [b][k][d] -> bf16 hi/lo [b][d][k] =================
__global__ void __launch_bounds__(256)
transpose_conv_kernel(const float* __restrict__ v,
                      __nv_bfloat16* __restrict__ th, __nv_bfloat16* __restrict__ tl)
{
    __shared__ float t[32][33];
    const int b  = blockIdx.z;
    const int k0 = blockIdx.x * 32;
    const int d0 = blockIdx.y * 32;
    const int tx = threadIdx.x & 31;
    const int ty = threadIdx.x >> 5;
#pragma unroll
    for (int i = 0; i < 4; i++) {
        int k = ty + i * 8;
        t[k][tx] = v[((size_t)b * Kn + k0 + k) * Dn + d0 + tx];
    }
    __syncthreads();
#pragma unroll
    for (int i = 0; i < 4; i++) {
        int d = ty + i * 8;
        float x = t[tx][d];
        __nv_bfloat16 hb = __float2bfloat16_rn(x);
        __nv_bfloat16 lb = __float2bfloat16_rn(x - __bfloat162float(hb));
        size_t o = ((size_t)b * Dn + d0 + d) * Kn + k0 + tx;
        th[o] = hb;
        tl[o] = lb;
    }
}

// ================= K1: E = exp(masked scores) + partial row sums =================
// 512 threads, CTA tile M=128 x N=256, K-dim = D = 128 (4-quarter cp.async pipeline).
#define K1S 136                    /* bf16 row stride */
#define OFF_QH 0
#define OFF_QL (128 * K1S * 2)                 /* 34816 */
#define OFF_KH (2 * 128 * K1S * 2)             /* 69632 */
#define OFF_KL (OFF_KH + 256 * K1S * 2)        /* 139264 */
#define K1_SMEM (OFF_KL + 256 * K1S * 2)       /* 208896 */

__global__ void __launch_bounds__(512, 1)
scores_kernel(const __nv_bfloat16* __restrict__ qh, const __nv_bfloat16* __restrict__ ql,
              const __nv_bfloat16* __restrict__ kh, const __nv_bfloat16* __restrict__ kl,
              const int* __restrict__ vlg,
              float* __restrict__ eg, float* __restrict__ ps)
{
    extern __shared__ unsigned char sm[];
    __nv_bfloat16* sQh = (__nv_bfloat16*)(sm + OFF_QH);
    __nv_bfloat16* sQl = (__nv_bfloat16*)(sm + OFF_QL);
    __nv_bfloat16* sKh = (__nv_bfloat16*)(sm + OFF_KH);
    __nv_bfloat16* sKl = (__nv_bfloat16*)(sm + OFF_KL);

    const int b  = blockIdx.z;
    const int i0 = blockIdx.y * 128;
    const int j0 = blockIdx.x * 256;
    const int tid = threadIdx.x;
    const int w = tid >> 5, lane = tid & 31;
    const int g = lane >> 2, ct = lane & 3;
    const int wm = w >> 2, wn = w & 3;        // 4x4 warp grid
    const int m0 = wm * 32, n0 = wn * 64;
    const int VL = vlg[b];

    const __nv_bfloat16* bq_h = qh + ((size_t)b * Qn + i0) * Dn;
    const __nv_bfloat16* bq_l = ql + ((size_t)b * Qn + i0) * Dn;
    const __nv_bfloat16* bk_h = kh + ((size_t)b * Kn + j0) * Dn;
    const __nv_bfloat16* bk_l = kl + ((size_t)b * Kn + j0) * Dn;
    const uint32_t uQh = smem_u32(sQh), uQl = smem_u32(sQl);
    const uint32_t uKh = smem_u32(sKh), uKl = smem_u32(sKl);

    // 4 commit groups, one per D-quarter (cols q*32 .. q*32+31)
#pragma unroll
    for (int q = 0; q < 4; q++) {
        {   // Qh, Ql: 512 ops each
            int r = tid >> 2, cc = tid & 3;
            int dsto = r * (K1S * 2) + (q * 4 + cc) * 16;
            size_t srco = (size_t)r * Dn + q * 32 + cc * 8;
            cpasync16(uQh + dsto, bq_h + srco);
            cpasync16(uQl + dsto, bq_l + srco);
        }
#pragma unroll
        for (int rep = 0; rep < 2; rep++) {   // Kh, Kl: 1024 ops each
            int idx = tid + rep * 512;
            int r = idx >> 2, cc = idx & 3;
            int dsto = r * (K1S * 2) + (q * 4 + cc) * 16;
            size_t srco = (size_t)r * Dn + q * 32 + cc * 8;
            cpasync16(uKh + dsto, bk_h + srco);
            cpasync16(uKl + dsto, bk_l + srco);
        }
        CP_COMMIT;
    }

    float acc[2][8][4] = {};
#pragma unroll
    for (int q = 0; q < 4; q++) {
        if (q == 0)      asm volatile("cp.async.wait_group 3;\n" ::: "memory");
        else if (q == 1) asm volatile("cp.async.wait_group 2;\n" ::: "memory");
        else if (q == 2) asm volatile("cp.async.wait_group 1;\n" ::: "memory");
        else             asm volatile("cp.async.wait_group 0;\n" ::: "memory");
        __syncthreads();
#pragma unroll
        for (int kt = 0; kt < 2; kt++) {
            const int kk = q * 2 + kt;
            uint32_t ah[2][4], al[2][4];
#pragma unroll
            for (int mf = 0; mf < 2; mf++) {
                const __nv_bfloat16* p0 = sQh + (m0 + mf * 16 + g) * K1S + kk * 16 + 2 * ct;
                ah[mf][0] = *(const uint32_t*)p0;
                ah[mf][1] = *(const uint32_t*)(p0 + 8 * K1S);
                ah[mf][2] = *(const uint32_t*)(p0 + 8);
                ah[mf][3] = *(const uint32_t*)(p0 + 8 * K1S + 8);
                const __nv_bfloat16* p1 = sQl + (m0 + mf * 16 + g) * K1S + kk * 16 + 2 * ct;
                al[mf][0] = *(const uint32_t*)p1;
                al[mf][1] = *(const uint32_t*)(p1 + 8 * K1S);
                al[mf][2] = *(const uint32_t*)(p1 + 8);
                al[mf][3] = *(const uint32_t*)(p1 + 8 * K1S + 8);
            }
#pragma unroll
            for (int nf = 0; nf < 8; nf++) {
                const __nv_bfloat16* kb = sKh + (n0 + nf * 8 + g) * K1S + kk * 16 + 2 * ct;
                uint32_t bh0 = *(const uint32_t*)kb;
                uint32_t bh1 = *(const uint32_t*)(kb + 8);
                const __nv_bfloat16* kc = sKl + (n0 + nf * 8 + g) * K1S + kk * 16 + 2 * ct;
                uint32_t bl0 = *(const uint32_t*)kc;
                uint32_t bl1 = *(const uint32_t*)(kc + 8);
#pragma unroll
                for (int mf = 0; mf < 2; mf++) {
                    MMA_BF16(acc[mf][nf], ah[mf][0], ah[mf][1], ah[mf][2], ah[mf][3], bh0, bh1);
                    MMA_BF16(acc[mf][nf], ah[mf][0], ah[mf][1], ah[mf][2], ah[mf][3], bl0, bl1);
                    MMA_BF16(acc[mf][nf], al[mf][0], al[mf][1], al[mf][2], al[mf][3], bh0, bh1);
                }
            }
        }
    }

    // ---- epilogue: scale, mask, exp, store E, partial sums ----
    const float scale = 0.08838834764831845f;  // 1/sqrt(128)
    const float mval = (VL == 0) ? 1.0f : 0.0f;
    const int jt = blockIdx.x * 4 + wn;        // 64-col block id
#pragma unroll
    for (int mf = 0; mf < 2; mf++) {
#pragma unroll
        for (int h = 0; h < 2; h++) {
            const int r = m0 + mf * 16 + h * 8 + g;
            float* erow = eg + ((size_t)b * Qn + i0 + r) * Kn + j0 + n0;
            float se = 0.f;
#pragma unroll
            for (int nf = 0; nf < 8; nf++) {
                int j = j0 + n0 + nf * 8 + 2 * ct;
                float e0 = (j     < VL) ? __expf(acc[mf][nf][2 * h]     * scale) : mval;
                float e1 = (j + 1 < VL) ? __expf(acc[mf][nf][2 * h + 1] * scale) : mval;
                *(float2*)(erow + nf * 8 + 2 * ct) = make_float2(e0, e1);
                se += e0 + e1;
            }
            se += __shfl_xor_sync(0xffffffffu, se, 1);
            se += __shfl_xor_sync(0xffffffffu, se, 2);
            if (ct == 0)
                ps[((size_t)b * Qn + i0 + r) * 32 + jt] = se;
        }
    }
}

// ================= K1b: reduce partials -> 1/row sum =================
__global__ void __launch_bounds__(256)
reduce_kernel(const float* __restrict__ ps, float* __restrict__ iso)
{
    int i = blockIdx.x * 256 + threadIdx.x;   // row id
    const float4* s4 = (const float4*)(ps + (size_t)i * 32);
    float sum = 0.f;
#pragma unroll
    for (int t = 0; t < 8; t++) {
        float4 sv = s4[t];
        sum += (sv.x + sv.y) + (sv.z + sv.w);
    }
    iso[i] = 1.0f / sum;
}

// ================= K2: normalize + attn writeback + PV GEMM =================
#define PS 68     /* float stride, E tile (k-contiguous) */
#define VS 72     /* bf16 stride, Vt tile rows d, cols k  */
#define K2_OFF_S  0
#define K2_SZ_S   (128 * PS * 4)          /* 34816 */
#define K2_OFF_VH (K2_SZ_S)
#define K2_SZ_V   (128 * VS * 2)          /* 18432 */
#define K2_OFF_VL (K2_OFF_VH + K2_SZ_V)
#define K2_OFF_IV (K2_OFF_VL + K2_SZ_V)
#define K2_SMEM   (K2_OFF_IV + 128 * 4)   /* 72192 */

__global__ void __launch_bounds__(256, 2)
pv_kernel(float* __restrict__ att,                     // in: E values, out: attn
          const __nv_bfloat16* __restrict__ vth, const __nv_bfloat16* __restrict__ vtl,
          const float* __restrict__ isg,
          float* __restrict__ outg)
{
    extern __shared__ unsigned char sm[];
    float*         sS  = (float*)(sm + K2_OFF_S);
    __nv_bfloat16* sVh = (__nv_bfloat16*)(sm + K2_OFF_VH);
    __nv_bfloat16* sVl = (__nv_bfloat16*)(sm + K2_OFF_VL);
    float*         sIv = (float*)(sm + K2_OFF_IV);

    const int b  = blockIdx.y;
    const int i0 = blockIdx.x * 128;
    const int tid = threadIdx.x;
    const int w = tid >> 5, lane = tid & 31;
    const int g = lane >> 2, ct = lane & 3;
    const int wm = w >> 1, wn = w & 1;

    float* Sg = att + ((size_t)b * Qn + i0) * Kn;
    const __nv_bfloat16* vh_g = vth + (size_t)b * Dn * Kn;
    const __nv_bfloat16* vl_g = vtl + (size_t)b * Dn * Kn;
    uint32_t sS_u  = smem_u32(sS);
    uint32_t sVh_u = smem_u32(sVh);
    uint32_t sVl_u = smem_u32(sVl);

    if (tid < 128) sIv[tid] = isg[(size_t)b * Qn + i0 + tid];

    // per-thread row inverse sums for frag rows
    float ris[2][2];
#pragma unroll
    for (int mf = 0; mf < 2; mf++)
#pragma unroll
        for (int h = 0; h < 2; h++)
            ris[mf][h] = isg[(size_t)b * Qn + i0 + wm * 32 + mf * 16 + h * 8 + g];

    float acc[2][8][4] = {};

    for (int c0 = 0; c0 < Kn; c0 += 64) {
        __syncthreads();
        // E chunk: 128 rows x 64 floats
#pragma unroll
        for (int rep = 0; rep < 8; rep++) {
            int idx = tid + rep * 256;
            int r = idx >> 4, c4 = idx & 15;
            cpasync16(sS_u + r * (PS * 4) + c4 * 16, Sg + (size_t)r * Kn + c0 + c4 * 4);
        }
        // Vt chunks: hi/lo, 128 d-rows x 64 bf16
#pragma unroll
        for (int rep = 0; rep < 8; rep++) {
            int arr = rep >> 2;
            int rem = tid + (rep & 3) * 256;
            int d = rem >> 3, c4 = rem & 7;
            if (arr == 0)
                cpasync16(sVh_u + d * (VS * 2) + c4 * 16, vh_g + (size_t)d * Kn + c0 + c4 * 8);
            else
                cpasync16(sVl_u + d * (VS * 2) + c4 * 16, vl_g + (size_t)d * Kn + c0 + c4 * 8);
        }
        CP_COMMIT; CP_WAIT0;
        __syncthreads();

        // normalized-attn writeback (each element exactly once, coalesced)
#pragma unroll
        for (int rep = 0; rep < 8; rep++) {
            int idx = tid + rep * 256;
            int r = idx >> 4, c4 = idx & 15;
            float iv = sIv[r];
            float4 e = *(const float4*)(sS + r * PS + c4 * 4);
            e.x *= iv; e.y *= iv; e.z *= iv; e.w *= iv;
            *(float4*)(Sg + (size_t)r * Kn + c0 + c4 * 4) = e;
        }

#pragma unroll
        for (int kk = 0; kk < 4; kk++) {
            uint32_t ah[2][4], al[2][4];
#pragma unroll
            for (int mf = 0; mf < 2; mf++) {
                const float* sp = sS + (wm * 32 + mf * 16 + g) * PS + kk * 16 + 2 * ct;
                float2 s0 = *(const float2*)sp;
                float2 s1 = *(const float2*)(sp + 8 * PS);
                float2 s2 = *(const float2*)(sp + 8);
                float2 s3 = *(const float2*)(sp + 8 * PS + 8);
                float i0v = ris[mf][0], i1v = ris[mf][1];
                splitpack(s0.x * i0v, s0.y * i0v, ah[mf][0], al[mf][0]);
                splitpack(s1.x * i1v, s1.y * i1v, ah[mf][1], al[mf][1]);
                splitpack(s2.x * i0v, s2.y * i0v, ah[mf][2], al[mf][2]);
                splitpack(s3.x * i1v, s3.y * i1v, ah[mf][3], al[mf][3]);
            }
#pragma unroll
            for (int nf = 0; nf < 8; nf++) {
                const __nv_bfloat16* vb = sVh + (wn * 64 + nf * 8 + g) * VS + kk * 16 + 2 * ct;
                uint32_t bh0 = *(const uint32_t*)vb;
                uint32_t bh1 = *(const uint32_t*)(vb + 8);
                const __nv_bfloat16* vc = sVl + (wn * 64 + nf * 8 + g) * VS + kk * 16 + 2 * ct;
                uint32_t bl0 = *(const uint32_t*)vc;
                uint32_t bl1 = *(const uint32_t*)(vc + 8);
#pragma unroll
                for (int mf = 0; mf < 2; mf++) {
                    MMA_BF16(acc[mf][nf], ah[mf][0], ah[mf][1], ah[mf][2], ah[mf][3], bh0, bh1);
                    MMA_BF16(acc[mf][nf], ah[mf][0], ah[mf][1], ah[mf][2], ah[mf][3], bl0, bl1);
                    MMA_BF16(acc[mf][nf], al[mf][0], al[mf][1], al[mf][2], al[mf][3], bh0, bh1);
                }
            }
        }
    }

    float* op = outg + ((size_t)b * Qn + i0) * Dn;
#pragma unroll
    for (int mf = 0; mf < 2; mf++)
#pragma unroll
        for (int nf = 0; nf < 8; nf++) {
            int row = wm * 32 + mf * 16 + g;
            int col = wn * 64 + nf * 8 + 2 * ct;
            *(float2*)(op + (size_t)row * Dn + col)       = make_float2(acc[mf][nf][0], acc[mf][nf][1]);
            *(float2*)(op + (size_t)(row + 8) * Dn + col) = make_float2(acc[mf][nf][2], acc[mf][nf][3]);
        }
}

// ================= launch =================
extern "C" void kernel_launch(void* const* d_in, const int* in_sizes, int n_in,
                              void* d_out, int out_size) {
    const float* q  = (const float*)d_in[0];
    const float* k  = (const float*)d_in[1];
    const float* v  = (const float*)d_in[2];
    const int*   vl = (const int*)d_in[3];
    float* out  = (float*)d_out;
    float* attn = out + (size_t)Bn * Qn * Dn;   // output tuple: (out, attn)

    void *p_qh, *p_ql, *p_kh, *p_kl, *p_vth, *p_vtl, *p_ps, *p_is;
    cudaGetSymbolAddress(&p_qh, g_qh);
    cudaGetSymbolAddress(&p_ql, g_ql);
    cudaGetSymbolAddress(&p_kh, g_kh);
    cudaGetSymbolAddress(&p_kl, g_kl);
    cudaGetSymbolAddress(&p_vth, g_vth);
    cudaGetSymbolAddress(&p_vtl, g_vtl);
    cudaGetSymbolAddress(&p_ps, g_ps);
    cudaGetSymbolAddress(&p_is, g_is);

    cudaFuncSetAttribute(scores_kernel, cudaFuncAttributeMaxDynamicSharedMemorySize, K1_SMEM);
    cudaFuncSetAttribute(pv_kernel,     cudaFuncAttributeMaxDynamicSharedMemorySize, K2_SMEM);

    const int n4 = Bn * Qn * Dn / 4;
    convert_kernel<<<n4 / 256, 256>>>(q, (__nv_bfloat16*)p_qh, (__nv_bfloat16*)p_ql);
    convert_kernel<<<n4 / 256, 256>>>(k, (__nv_bfloat16*)p_kh, (__nv_bfloat16*)p_kl);
    transpose_conv_kernel<<<dim3(Kn / 32, Dn / 32, Bn), 256>>>(v, (__nv_bfloat16*)p_vth,
                                                               (__nv_bfloat16*)p_vtl);

    scores_kernel<<<dim3(Kn / 256, Qn / 128, Bn), 512, K1_SMEM>>>(
        (const __nv_bfloat16*)p_qh, (const __nv_bfloat16*)p_ql,
        (const __nv_bfloat16*)p_kh, (const __nv_bfloat16*)p_kl,
        vl, attn, (float*)p_ps);

    reduce_kernel<<<Bn * Qn / 256, 256>>>((const float*)p_ps, (float*)p_is);

    pv_kernel<<<dim3(Qn / 128, Bn), 256, K2_SMEM>>>(
        attn, (const __nv_bfloat16*)p_vth, (const __nv_bfloat16*)p_vtl,
        (const float*)p_is, out);
}